// round 2
// baseline (speedup 1.0000x reference)
#include <cuda_runtime.h>
#include <math.h>

// Problem constants
#define BB 8
#define CC 128
#define HWM 4096          // H*W = 64*64
#define TN 64             // K/V tile (columns of n)
#define NTHREADS 256

// Folded classifier-head weights (BN folded into w1), built by prep_kernel.
__device__ float g_At[3 * CC * CC];   // At[c][o] = w1[o][c] * inv[o], c in [0,384), o in [0,128)
__device__ float g_dv[CC];            // dv[o] = b1[o]*inv[o] + beta[o] - mean[o]*inv[o]

__global__ void prep_kernel(const float* __restrict__ w1, const float* __restrict__ b1,
                            const float* __restrict__ gamma, const float* __restrict__ beta,
                            const float* __restrict__ rmean, const float* __restrict__ rvar)
{
    int i = blockIdx.x * blockDim.x + threadIdx.x;
    if (i < 3 * CC * CC) {
        int c = i / CC;
        int o = i % CC;
        float inv = gamma[o] * rsqrtf(rvar[o] + 1e-5f);
        g_At[c * CC + o] = w1[o * (3 * CC) + c] * inv;
    }
    if (i < CC) {
        float inv = gamma[i] * rsqrtf(rvar[i] + 1e-5f);
        g_dv[i] = b1[i] * inv + beta[i] - rmean[i] * inv;
    }
}

// Fused dual-attention + cls head.
// Grid: (HWM/32, BB). Block: 256 threads = 16x16 (tx = col-group, ty = row-group).
// Per CTA: 32 query positions m0..m0+31 of batch b.
//   Logical query rows r in [0,64): r<32 -> Q = ref (cross-attn / feats0),
//                                   r>=32 -> Q = cur (self-attn / feats1).
// Streams K=V=cur in 64-wide tiles with online softmax; feats accumulate in regs.
// Epilogue: x = [feats0; feats1; cur] (384), y = At^T... y_o = sum_c At[c][o]*x[c] + dv[o],
// leaky(0.01), pred = sum_o w2[o]*leaky(y_o) + b2.
//
// Shared memory layout (dynamic, 99328 bytes):
//   Qs : [128][64]  floats at offset 0      (8192 floats)  queries, k-major, pre-scaled
//   Ks : [128][64]  floats at offset 8192   (8192 floats)  K tile, k-major
//   KsT: [64][132]  floats at offset 16384  (8448 floats)  K tile transposed (j-major)
//   Ps : [64][68]   floats  -- ALIASES Ks (used after S-phase reads of Ks complete)
// Epilogue reuses the whole region:
//   Xs : [384][36] at offset 0, Ys : [128][33] at offset 13824.

__global__ void __launch_bounds__(NTHREADS, 2)
fused_attn_kernel(const float* __restrict__ reff, const float* __restrict__ curf,
                  const float* __restrict__ w2, const float* __restrict__ b2,
                  float* __restrict__ out)
{
    extern __shared__ float sm[];
    float* Qs  = sm;            // 8192
    float* Ks  = sm + 8192;     // 8192
    float* KsT = sm + 16384;    // 8448
    float* Ps  = Ks;            // alias (4352 <= 8192)

    const int b   = blockIdx.y;
    const int m0  = blockIdx.x * 32;
    const int tid = threadIdx.x;
    const int tx  = tid & 15;
    const int ty  = tid >> 4;

    const float* __restrict__ curb = curf + (size_t)b * CC * HWM;
    const float* __restrict__ refb = reff + (size_t)b * CC * HWM;

    const float scale = 0.08838834764831845f;  // 1/sqrt(128)

    // ---- Load Q tile (scaled). Rows 0..31 = ref, 32..63 = cur. ----
    for (int i = tid; i < CC * 64; i += NTHREADS) {
        int k = i >> 6;
        int r = i & 63;
        float v = (r < 32) ? refb[k * HWM + m0 + r]
                           : curb[k * HWM + m0 + (r - 32)];
        Qs[k * 64 + r] = v * scale;
    }

    // Accumulators: thread owns channels {tx*4..tx*4+3} U {64+tx*4..64+tx*4+3}
    // and logical rows {ty*4..ty*4+3}.
    float acc[8][4];
    #pragma unroll
    for (int ci = 0; ci < 8; ci++)
        #pragma unroll
        for (int ri = 0; ri < 4; ri++) acc[ci][ri] = 0.0f;

    float m_i[4], l_i[4];
    #pragma unroll
    for (int ri = 0; ri < 4; ri++) { m_i[ri] = -INFINITY; l_i[ri] = 0.0f; }

    // ---- Main loop over K/V tiles ----
    for (int nt = 0; nt < HWM / TN; nt++) {
        const int n0 = nt * TN;

        __syncthreads();  // previous PV reads of Ps/KsT done before overwrite
        for (int i = tid; i < CC * TN; i += NTHREADS) {
            int k = i >> 6;
            int j = i & 63;
            float v = curb[k * HWM + n0 + j];
            Ks[k * 64 + j]   = v;
            KsT[j * 132 + k] = v;
        }
        __syncthreads();

        // S = Q^T K  (64 x 64 tile, 4x4 per thread)
        float s[4][4];
        #pragma unroll
        for (int ri = 0; ri < 4; ri++)
            #pragma unroll
            for (int ci = 0; ci < 4; ci++) s[ri][ci] = 0.0f;

        #pragma unroll 4
        for (int k = 0; k < CC; k++) {
            float4 q  = *(const float4*)(Qs + k * 64 + ty * 4);
            float4 kv = *(const float4*)(Ks + k * 64 + tx * 4);
            float qa[4] = {q.x, q.y, q.z, q.w};
            float kb[4] = {kv.x, kv.y, kv.z, kv.w};
            #pragma unroll
            for (int ri = 0; ri < 4; ri++)
                #pragma unroll
                for (int ci = 0; ci < 4; ci++)
                    s[ri][ci] += qa[ri] * kb[ci];
        }

        // Online softmax (row stats across the 16 tx lanes; xor<=8 stays in half-warp)
        float rmax[4], rsum[4], alpha[4];
        #pragma unroll
        for (int ri = 0; ri < 4; ri++) {
            float mx = s[ri][0];
            mx = fmaxf(mx, s[ri][1]);
            mx = fmaxf(mx, s[ri][2]);
            mx = fmaxf(mx, s[ri][3]);
            rmax[ri] = mx;
        }
        #pragma unroll
        for (int off = 1; off < 16; off <<= 1)
            #pragma unroll
            for (int ri = 0; ri < 4; ri++)
                rmax[ri] = fmaxf(rmax[ri], __shfl_xor_sync(0xffffffffu, rmax[ri], off));

        #pragma unroll
        for (int ri = 0; ri < 4; ri++) {
            float mn = fmaxf(m_i[ri], rmax[ri]);
            alpha[ri] = __expf(m_i[ri] - mn);   // exp(-inf)=0 on first tile
            m_i[ri] = mn;
            rsum[ri] = 0.0f;
        }
        #pragma unroll
        for (int ri = 0; ri < 4; ri++)
            #pragma unroll
            for (int ci = 0; ci < 4; ci++) {
                float p = __expf(s[ri][ci] - m_i[ri]);
                s[ri][ci] = p;
                rsum[ri] += p;
            }
        #pragma unroll
        for (int off = 1; off < 16; off <<= 1)
            #pragma unroll
            for (int ri = 0; ri < 4; ri++)
                rsum[ri] += __shfl_xor_sync(0xffffffffu, rsum[ri], off);

        #pragma unroll
        for (int ri = 0; ri < 4; ri++)
            l_i[ri] = l_i[ri] * alpha[ri] + rsum[ri];

        #pragma unroll
        for (int ci = 0; ci < 8; ci++)
            #pragma unroll
            for (int ri = 0; ri < 4; ri++)
                acc[ci][ri] *= alpha[ri];

        __syncthreads();  // all S-phase reads of Ks done (Ps aliases Ks)

        // Stage P (unnormalized) to smem, j-major: Ps[j][r]
        #pragma unroll
        for (int ci = 0; ci < 4; ci++) {
            int j = tx * 4 + ci;
            *(float4*)(Ps + j * 68 + ty * 4) =
                make_float4(s[0][ci], s[1][ci], s[2][ci], s[3][ci]);
        }
        __syncthreads();

        // feats += P * V  (V = K tile, read via KsT)
        #pragma unroll 2
        for (int j = 0; j < TN; j++) {
            float4 p4 = *(const float4*)(Ps + j * 68 + ty * 4);
            float4 v0 = *(const float4*)(KsT + j * 132 + tx * 4);
            float4 v1 = *(const float4*)(KsT + j * 132 + 64 + tx * 4);
            float pr[4] = {p4.x, p4.y, p4.z, p4.w};
            float va[8] = {v0.x, v0.y, v0.z, v0.w, v1.x, v1.y, v1.z, v1.w};
            #pragma unroll
            for (int ci = 0; ci < 8; ci++)
                #pragma unroll
                for (int ri = 0; ri < 4; ri++)
                    acc[ci][ri] += va[ci] * pr[ri];
        }
    }
    __syncthreads();  // attention done; smem free for epilogue

    // ---- Epilogue: build X = [feats0; feats1; cur] in smem ----
    float* Xs = sm;            // [384][36]
    float* Ys = sm + 384 * 36; // [128][33]

    float rl[4];
    #pragma unroll
    for (int ri = 0; ri < 4; ri++) rl[ri] = 1.0f / l_i[ri];

    #pragma unroll
    for (int ci = 0; ci < 8; ci++) {
        int c = (ci < 4) ? (tx * 4 + ci) : (64 + tx * 4 + (ci - 4));
        #pragma unroll
        for (int ri = 0; ri < 4; ri++) {
            int r  = ty * 4 + ri;
            int a  = r >> 5;      // 0 = feats0 (ref-query), 1 = feats1 (cur-query)
            int ml = r & 31;
            Xs[(a * CC + c) * 36 + ml] = acc[ci][ri] * rl[ri];
        }
    }
    for (int i = tid; i < CC * 32; i += NTHREADS) {
        int c  = i >> 5;
        int ml = i & 31;
        Xs[(2 * CC + c) * 36 + ml] = curb[c * HWM + m0 + ml];
    }
    __syncthreads();

    // y[o][m] = sum_c At[c][o] * X[c][m] + dv[o]; then leaky, premultiply by w2[o]
    {
        int o    = tid & 127;
        int half = tid >> 7;     // 0/1 -> m-range halves
        float y[16];
        float dv = g_dv[o];
        #pragma unroll
        for (int q = 0; q < 16; q++) y[q] = dv;

        #pragma unroll 4
        for (int c = 0; c < 3 * CC; c++) {
            float a = g_At[c * CC + o];
            const float4* xp = (const float4*)(Xs + c * 36 + half * 16);
            float4 x0 = xp[0], x1 = xp[1], x2 = xp[2], x3 = xp[3];
            y[0]  += a * x0.x; y[1]  += a * x0.y; y[2]  += a * x0.z; y[3]  += a * x0.w;
            y[4]  += a * x1.x; y[5]  += a * x1.y; y[6]  += a * x1.z; y[7]  += a * x1.w;
            y[8]  += a * x2.x; y[9]  += a * x2.y; y[10] += a * x2.z; y[11] += a * x2.w;
            y[12] += a * x3.x; y[13] += a * x3.y; y[14] += a * x3.z; y[15] += a * x3.w;
        }
        float w2o = w2[o];
        #pragma unroll
        for (int q = 0; q < 16; q++) {
            float v = y[q];
            v = (v > 0.0f) ? v : 0.01f * v;
            Ys[o * 33 + half * 16 + q] = w2o * v;
        }
    }
    __syncthreads();

    if (tid < 32) {
        float ssum = b2[0];
        #pragma unroll 4
        for (int o = 0; o < CC; o++) ssum += Ys[o * 33 + tid];
        out[b * HWM + m0 + tid] = ssum;
    }
}

extern "C" void kernel_launch(void* const* d_in, const int* in_sizes, int n_in,
                              void* d_out, int out_size)
{
    const float* ref_feat = (const float*)d_in[0];
    const float* cur_feat = (const float*)d_in[1];
    const float* w1       = (const float*)d_in[2];
    const float* b1       = (const float*)d_in[3];
    const float* gamma    = (const float*)d_in[4];
    const float* beta     = (const float*)d_in[5];
    const float* rmean    = (const float*)d_in[6];
    const float* rvar     = (const float*)d_in[7];
    const float* w2       = (const float*)d_in[8];
    const float* b2       = (const float*)d_in[9];
    float* out            = (float*)d_out;

    // Fold BN into w1 (tiny).
    prep_kernel<<<(3 * CC * CC + 255) / 256, 256>>>(w1, b1, gamma, beta, rmean, rvar);

    const int smem_bytes = (8192 + 8192 + 64 * 132) * 4;  // 99328
    cudaFuncSetAttribute(fused_attn_kernel,
                         cudaFuncAttributeMaxDynamicSharedMemorySize, smem_bytes);

    dim3 grid(HWM / 32, BB);
    fused_attn_kernel<<<grid, NTHREADS, smem_bytes>>>(ref_feat, cur_feat, w2, b2, out);
}

// round 3
// speedup vs baseline: 1.0001x; 1.0001x over previous
#include <cuda_runtime.h>
#include <math.h>

// Problem constants
#define BB 8
#define CC 128
#define HWM 4096          // H*W = 64*64
#define TN 64             // K/V tile (columns of n)
#define NTHREADS 256

// Folded classifier-head weights (BN folded into w1), built by prep_kernel.
__device__ float g_At[3 * CC * CC];   // At[c][o] = w1[o][c] * inv[o], c in [0,384), o in [0,128)
__device__ float g_dv[CC];            // dv[o] = b1[o]*inv[o] + beta[o] - mean[o]*inv[o]

__global__ void prep_kernel(const float* __restrict__ w1, const float* __restrict__ b1,
                            const float* __restrict__ gamma, const float* __restrict__ beta,
                            const float* __restrict__ rmean, const float* __restrict__ rvar)
{
    int i = blockIdx.x * blockDim.x + threadIdx.x;
    if (i < 3 * CC * CC) {
        int c = i / CC;
        int o = i % CC;
        float inv = gamma[o] * rsqrtf(rvar[o] + 1e-5f);
        g_At[c * CC + o] = w1[o * (3 * CC) + c] * inv;
    }
    if (i < CC) {
        float inv = gamma[i] * rsqrtf(rvar[i] + 1e-5f);
        g_dv[i] = b1[i] * inv + beta[i] - rmean[i] * inv;
    }
}

// Fused dual-attention + cls head.
// Grid: (HWM/32, BB). Block: 256 threads = 16x16 (tx = col-group, ty = row-group).
// Per CTA: 32 query positions m0..m0+31 of batch b.
//   Logical query rows r in [0,64): r<32 -> Q = ref (cross-attn / feats0),
//                                   r>=32 -> Q = cur (self-attn / feats1).
// Streams K=V=cur in 64-wide tiles with online softmax; feats accumulate in regs.
// Epilogue: x = [feats0; feats1; cur] (384), y = At^T... y_o = sum_c At[c][o]*x[c] + dv[o],
// leaky(0.01), pred = sum_o w2[o]*leaky(y_o) + b2.
//
// Shared memory layout (dynamic, 99328 bytes):
//   Qs : [128][64]  floats at offset 0      (8192 floats)  queries, k-major, pre-scaled
//   Ks : [128][64]  floats at offset 8192   (8192 floats)  K tile, k-major
//   KsT: [64][132]  floats at offset 16384  (8448 floats)  K tile transposed (j-major)
//   Ps : [64][68]   floats  -- ALIASES Ks (used after S-phase reads of Ks complete)
// Epilogue reuses the whole region:
//   Xs : [384][36] at offset 0, Ys : [128][33] at offset 13824.

__global__ void __launch_bounds__(NTHREADS, 2)
fused_attn_kernel(const float* __restrict__ reff, const float* __restrict__ curf,
                  const float* __restrict__ w2, const float* __restrict__ b2,
                  float* __restrict__ out)
{
    extern __shared__ float sm[];
    float* Qs  = sm;            // 8192
    float* Ks  = sm + 8192;     // 8192
    float* KsT = sm + 16384;    // 8448
    float* Ps  = Ks;            // alias (4352 <= 8192)

    const int b   = blockIdx.y;
    const int m0  = blockIdx.x * 32;
    const int tid = threadIdx.x;
    const int tx  = tid & 15;
    const int ty  = tid >> 4;

    const float* __restrict__ curb = curf + (size_t)b * CC * HWM;
    const float* __restrict__ refb = reff + (size_t)b * CC * HWM;

    const float scale = 0.08838834764831845f;  // 1/sqrt(128)

    // ---- Load Q tile (scaled). Rows 0..31 = ref, 32..63 = cur. ----
    for (int i = tid; i < CC * 64; i += NTHREADS) {
        int k = i >> 6;
        int r = i & 63;
        float v = (r < 32) ? refb[k * HWM + m0 + r]
                           : curb[k * HWM + m0 + (r - 32)];
        Qs[k * 64 + r] = v * scale;
    }

    // Accumulators: thread owns channels {tx*4..tx*4+3} U {64+tx*4..64+tx*4+3}
    // and logical rows {ty*4..ty*4+3}.
    float acc[8][4];
    #pragma unroll
    for (int ci = 0; ci < 8; ci++)
        #pragma unroll
        for (int ri = 0; ri < 4; ri++) acc[ci][ri] = 0.0f;

    float m_i[4], l_i[4];
    #pragma unroll
    for (int ri = 0; ri < 4; ri++) { m_i[ri] = -INFINITY; l_i[ri] = 0.0f; }

    // ---- Main loop over K/V tiles ----
    for (int nt = 0; nt < HWM / TN; nt++) {
        const int n0 = nt * TN;

        __syncthreads();  // previous PV reads of Ps/KsT done before overwrite
        for (int i = tid; i < CC * TN; i += NTHREADS) {
            int k = i >> 6;
            int j = i & 63;
            float v = curb[k * HWM + n0 + j];
            Ks[k * 64 + j]   = v;
            KsT[j * 132 + k] = v;
        }
        __syncthreads();

        // S = Q^T K  (64 x 64 tile, 4x4 per thread)
        float s[4][4];
        #pragma unroll
        for (int ri = 0; ri < 4; ri++)
            #pragma unroll
            for (int ci = 0; ci < 4; ci++) s[ri][ci] = 0.0f;

        #pragma unroll 4
        for (int k = 0; k < CC; k++) {
            float4 q  = *(const float4*)(Qs + k * 64 + ty * 4);
            float4 kv = *(const float4*)(Ks + k * 64 + tx * 4);
            float qa[4] = {q.x, q.y, q.z, q.w};
            float kb[4] = {kv.x, kv.y, kv.z, kv.w};
            #pragma unroll
            for (int ri = 0; ri < 4; ri++)
                #pragma unroll
                for (int ci = 0; ci < 4; ci++)
                    s[ri][ci] += qa[ri] * kb[ci];
        }

        // Online softmax (row stats across the 16 tx lanes; xor<=8 stays in half-warp)
        float rmax[4], rsum[4], alpha[4];
        #pragma unroll
        for (int ri = 0; ri < 4; ri++) {
            float mx = s[ri][0];
            mx = fmaxf(mx, s[ri][1]);
            mx = fmaxf(mx, s[ri][2]);
            mx = fmaxf(mx, s[ri][3]);
            rmax[ri] = mx;
        }
        #pragma unroll
        for (int off = 1; off < 16; off <<= 1)
            #pragma unroll
            for (int ri = 0; ri < 4; ri++)
                rmax[ri] = fmaxf(rmax[ri], __shfl_xor_sync(0xffffffffu, rmax[ri], off));

        #pragma unroll
        for (int ri = 0; ri < 4; ri++) {
            float mn = fmaxf(m_i[ri], rmax[ri]);
            alpha[ri] = __expf(m_i[ri] - mn);   // exp(-inf)=0 on first tile
            m_i[ri] = mn;
            rsum[ri] = 0.0f;
        }
        #pragma unroll
        for (int ri = 0; ri < 4; ri++)
            #pragma unroll
            for (int ci = 0; ci < 4; ci++) {
                float p = __expf(s[ri][ci] - m_i[ri]);
                s[ri][ci] = p;
                rsum[ri] += p;
            }
        #pragma unroll
        for (int off = 1; off < 16; off <<= 1)
            #pragma unroll
            for (int ri = 0; ri < 4; ri++)
                rsum[ri] += __shfl_xor_sync(0xffffffffu, rsum[ri], off);

        #pragma unroll
        for (int ri = 0; ri < 4; ri++)
            l_i[ri] = l_i[ri] * alpha[ri] + rsum[ri];

        #pragma unroll
        for (int ci = 0; ci < 8; ci++)
            #pragma unroll
            for (int ri = 0; ri < 4; ri++)
                acc[ci][ri] *= alpha[ri];

        __syncthreads();  // all S-phase reads of Ks done (Ps aliases Ks)

        // Stage P (unnormalized) to smem, j-major: Ps[j][r]
        #pragma unroll
        for (int ci = 0; ci < 4; ci++) {
            int j = tx * 4 + ci;
            *(float4*)(Ps + j * 68 + ty * 4) =
                make_float4(s[0][ci], s[1][ci], s[2][ci], s[3][ci]);
        }
        __syncthreads();

        // feats += P * V  (V = K tile, read via KsT)
        #pragma unroll 2
        for (int j = 0; j < TN; j++) {
            float4 p4 = *(const float4*)(Ps + j * 68 + ty * 4);
            float4 v0 = *(const float4*)(KsT + j * 132 + tx * 4);
            float4 v1 = *(const float4*)(KsT + j * 132 + 64 + tx * 4);
            float pr[4] = {p4.x, p4.y, p4.z, p4.w};
            float va[8] = {v0.x, v0.y, v0.z, v0.w, v1.x, v1.y, v1.z, v1.w};
            #pragma unroll
            for (int ci = 0; ci < 8; ci++)
                #pragma unroll
                for (int ri = 0; ri < 4; ri++)
                    acc[ci][ri] += va[ci] * pr[ri];
        }
    }
    __syncthreads();  // attention done; smem free for epilogue

    // ---- Epilogue: build X = [feats0; feats1; cur] in smem ----
    float* Xs = sm;            // [384][36]
    float* Ys = sm + 384 * 36; // [128][33]

    float rl[4];
    #pragma unroll
    for (int ri = 0; ri < 4; ri++) rl[ri] = 1.0f / l_i[ri];

    #pragma unroll
    for (int ci = 0; ci < 8; ci++) {
        int c = (ci < 4) ? (tx * 4 + ci) : (64 + tx * 4 + (ci - 4));
        #pragma unroll
        for (int ri = 0; ri < 4; ri++) {
            int r  = ty * 4 + ri;
            int a  = r >> 5;      // 0 = feats0 (ref-query), 1 = feats1 (cur-query)
            int ml = r & 31;
            Xs[(a * CC + c) * 36 + ml] = acc[ci][ri] * rl[ri];
        }
    }
    for (int i = tid; i < CC * 32; i += NTHREADS) {
        int c  = i >> 5;
        int ml = i & 31;
        Xs[(2 * CC + c) * 36 + ml] = curb[c * HWM + m0 + ml];
    }
    __syncthreads();

    // y[o][m] = sum_c At[c][o] * X[c][m] + dv[o]; then leaky, premultiply by w2[o]
    {
        int o    = tid & 127;
        int half = tid >> 7;     // 0/1 -> m-range halves
        float y[16];
        float dv = g_dv[o];
        #pragma unroll
        for (int q = 0; q < 16; q++) y[q] = dv;

        #pragma unroll 4
        for (int c = 0; c < 3 * CC; c++) {
            float a = g_At[c * CC + o];
            const float4* xp = (const float4*)(Xs + c * 36 + half * 16);
            float4 x0 = xp[0], x1 = xp[1], x2 = xp[2], x3 = xp[3];
            y[0]  += a * x0.x; y[1]  += a * x0.y; y[2]  += a * x0.z; y[3]  += a * x0.w;
            y[4]  += a * x1.x; y[5]  += a * x1.y; y[6]  += a * x1.z; y[7]  += a * x1.w;
            y[8]  += a * x2.x; y[9]  += a * x2.y; y[10] += a * x2.z; y[11] += a * x2.w;
            y[12] += a * x3.x; y[13] += a * x3.y; y[14] += a * x3.z; y[15] += a * x3.w;
        }
        float w2o = w2[o];
        #pragma unroll
        for (int q = 0; q < 16; q++) {
            float v = y[q];
            v = (v > 0.0f) ? v : 0.01f * v;
            Ys[o * 33 + half * 16 + q] = w2o * v;
        }
    }
    __syncthreads();

    if (tid < 32) {
        float ssum = b2[0];
        #pragma unroll 4
        for (int o = 0; o < CC; o++) ssum += Ys[o * 33 + tid];
        out[b * HWM + m0 + tid] = ssum;
    }
}

extern "C" void kernel_launch(void* const* d_in, const int* in_sizes, int n_in,
                              void* d_out, int out_size)
{
    const float* ref_feat = (const float*)d_in[0];
    const float* cur_feat = (const float*)d_in[1];
    const float* w1       = (const float*)d_in[2];
    const float* b1       = (const float*)d_in[3];
    const float* gamma    = (const float*)d_in[4];
    const float* beta     = (const float*)d_in[5];
    const float* rmean    = (const float*)d_in[6];
    const float* rvar     = (const float*)d_in[7];
    const float* w2       = (const float*)d_in[8];
    const float* b2       = (const float*)d_in[9];
    float* out            = (float*)d_out;

    // Fold BN into w1 (tiny).
    prep_kernel<<<(3 * CC * CC + 255) / 256, 256>>>(w1, b1, gamma, beta, rmean, rvar);

    const int smem_bytes = (8192 + 8192 + 64 * 132) * 4;  // 99328
    cudaFuncSetAttribute(fused_attn_kernel,
                         cudaFuncAttributeMaxDynamicSharedMemorySize, smem_bytes);

    dim3 grid(HWM / 32, BB);
    fused_attn_kernel<<<grid, NTHREADS, smem_bytes>>>(ref_feat, cur_feat, w2, b2, out);
}